// round 4
// baseline (speedup 1.0000x reference)
#include <cuda_runtime.h>
#include <cuda_bf16.h>
#include <cstdint>
#include <cstddef>

// ============================================================================
// MLP_SAT: factorized edge-MLP + segment mean
//   L = l_embs @ W1[:384] + b1        [131072, 256]   (tf32 mma GEMM)
//   C = c_embs @ W1[384:]             [65536, 256]    (tf32 mma GEMM)
//   per edge: h1 = relu(L[i] + C[j]); h2 = relu(h1@W2+b2); h3 = relu(h2@W3+b3)
//             w  = h3@W4 + b4 ; atomic segment sum/count per clause
//   out[e] = sums[edge_j[e]] / max(counts, 1)
//
// NOTE: g_L/g_C are selected INSIDE device code (template param) — passing a
// __device__ symbol from host code yields the host shadow address, which on
// GB300 (ATS) silently writes to host RAM instead of trapping.
// ============================================================================

#define NLITS_MAX   131072
#define NCLS_MAX    65536

__device__ float g_L[(size_t)NLITS_MAX * 256];
__device__ float g_C[(size_t)NCLS_MAX * 256];
__device__ float g_sums[NCLS_MAX];
__device__ float g_cnts[NCLS_MAX];

__device__ __forceinline__ unsigned f2tf(float x) {
    unsigned r;
    asm("cvt.rna.tf32.f32 %0, %1;" : "=r"(r) : "f"(x));
    return r;
}

__device__ __forceinline__ void mma_tf32(float* d, const unsigned* a, const unsigned* b) {
    asm volatile(
        "mma.sync.aligned.m16n8k8.row.col.f32.tf32.tf32.f32 "
        "{%0,%1,%2,%3}, {%4,%5,%6,%7}, {%8,%9}, {%0,%1,%2,%3};\n"
        : "+f"(d[0]), "+f"(d[1]), "+f"(d[2]), "+f"(d[3])
        : "r"(a[0]), "r"(a[1]), "r"(a[2]), "r"(a[3]), "r"(b[0]), "r"(b[1]));
}

// ----------------------------------------------------------------------------
// GEMM: out[M,256] = A[M,384] @ W[384,256] (+ bias). BM=128, BN=128, BK=32.
// 256 threads, 8 warps in 4(m) x 2(n); warp tile 32x64 (2 m-sub x 8 n-sub).
// BIAS=true -> writes g_L (with b1); BIAS=false -> writes g_C.
// ----------------------------------------------------------------------------
template<bool BIAS>
__global__ __launch_bounds__(256) void gemm384x256(
    const float* __restrict__ A, const float* __restrict__ W,
    const float* __restrict__ bias)
{
    float* __restrict__ out = BIAS ? g_L : g_C;   // device-side symbol ref

    __shared__ float As[128 * 36];   // row stride 36 -> bank = (4r + c) % 32
    __shared__ float Ws[32 * 132];   // row stride 132 -> bank = (4k + n) % 32

    const int tid  = threadIdx.x;
    const int warp = tid >> 5, lane = tid & 31;
    const int g = lane >> 2, t4 = lane & 3;
    const int wm = warp & 3, wn = warp >> 2;
    const int rowBase = blockIdx.x * 128;
    const int colBase = blockIdx.y * 128;

    float acc[2][8][4];
    #pragma unroll
    for (int mi = 0; mi < 2; mi++)
        #pragma unroll
        for (int ni = 0; ni < 8; ni++)
            #pragma unroll
            for (int q = 0; q < 4; q++) acc[mi][ni][q] = 0.f;

    for (int kt = 0; kt < 384; kt += 32) {
        #pragma unroll
        for (int s = 0; s < 4; s++) {           // A tile: 128x32 = 1024 float4
            int slot = tid + s * 256;
            int r = slot >> 3, c = slot & 7;
            float4 v = *(const float4*)&A[(size_t)(rowBase + r) * 384 + kt + c * 4];
            *(float4*)&As[r * 36 + c * 4] = v;
        }
        #pragma unroll
        for (int s = 0; s < 4; s++) {           // W tile: 32x128 = 1024 float4
            int slot = tid + s * 256;
            int r = slot >> 5, c = slot & 31;
            float4 v = *(const float4*)&W[(size_t)(kt + r) * 256 + colBase + c * 4];
            *(float4*)&Ws[r * 132 + c * 4] = v;
        }
        __syncthreads();

        #pragma unroll
        for (int k8 = 0; k8 < 4; k8++) {
            const int kc = k8 * 8;
            unsigned afr[2][4];
            #pragma unroll
            for (int mi = 0; mi < 2; mi++) {
                int rb = wm * 32 + mi * 16;
                afr[mi][0] = f2tf(As[(rb + g    ) * 36 + kc + t4    ]);
                afr[mi][1] = f2tf(As[(rb + g + 8) * 36 + kc + t4    ]);
                afr[mi][2] = f2tf(As[(rb + g    ) * 36 + kc + t4 + 4]);
                afr[mi][3] = f2tf(As[(rb + g + 8) * 36 + kc + t4 + 4]);
            }
            #pragma unroll
            for (int ni = 0; ni < 8; ni++) {
                unsigned bfr[2];
                int col = wn * 64 + ni * 8 + g;
                bfr[0] = f2tf(Ws[(kc + t4    ) * 132 + col]);
                bfr[1] = f2tf(Ws[(kc + t4 + 4) * 132 + col]);
                mma_tf32(acc[0][ni], afr[0], bfr);
                mma_tf32(acc[1][ni], afr[1], bfr);
            }
        }
        __syncthreads();
    }

    #pragma unroll
    for (int mi = 0; mi < 2; mi++) {
        #pragma unroll
        for (int ni = 0; ni < 8; ni++) {
            int r0 = rowBase + wm * 32 + mi * 16 + g;
            int c0 = colBase + wn * 64 + ni * 8 + t4 * 2;
            float bb0 = BIAS ? bias[c0] : 0.f;
            float bb1 = BIAS ? bias[c0 + 1] : 0.f;
            float2 v0 = {acc[mi][ni][0] + bb0, acc[mi][ni][1] + bb1};
            float2 v1 = {acc[mi][ni][2] + bb0, acc[mi][ni][3] + bb1};
            *(float2*)&out[(size_t)r0 * 256 + c0] = v0;
            *(float2*)&out[(size_t)(r0 + 8) * 256 + c0] = v1;
        }
    }
}

// ----------------------------------------------------------------------------
// Zero the per-clause accumulators (graph replay must be deterministic).
// ----------------------------------------------------------------------------
__global__ void zero_kernel(int n) {
    int i = blockIdx.x * blockDim.x + threadIdx.x;
    if (i < n) { g_sums[i] = 0.f; g_cnts[i] = 0.f; }
}

// ----------------------------------------------------------------------------
// Edge kernel: tile of 64 edges per block, 256 threads (8 warps).
// ----------------------------------------------------------------------------
#define EDGE_SMEM_FLOATS (64*260 + 256*68 + 64*68 + 64*36 + 64*36 + 64 + 24 + 20 + 4 + 128)
#define EDGE_SMEM_BYTES  (EDGE_SMEM_FLOATS * 4)

__global__ __launch_bounds__(256) void edge_kernel(
    const int* __restrict__ edge_i, const int* __restrict__ edge_j,
    const float* __restrict__ W2, const float* __restrict__ b2,
    const float* __restrict__ W3, const float* __restrict__ b3,
    const float* __restrict__ W4, const float* __restrict__ b4,
    int nE)
{
    extern __shared__ float sm[];
    float* h1  = sm;                 // 64*260
    float* W2s = h1  + 64 * 260;     // 256*68
    float* h2  = W2s + 256 * 68;     // 64*68
    float* W3s = h2  + 64 * 68;      // 64*36
    float* h3  = W3s + 64 * 36;      // 64*36
    float* b2s = h3  + 64 * 36;      // 64
    float* b3s = b2s + 64;           // 24
    float* W4s = b3s + 24;           // 20
    float* b4s = W4s + 20;           // 4
    int*   eis = (int*)(b4s + 4);    // 64 ints
    int*   ejs = eis + 64;           // 64 ints

    const int tid  = threadIdx.x;
    const int warp = tid >> 5, lane = tid & 31;
    const int g = lane >> 2, t4 = lane & 3;
    const int ebase = blockIdx.x * 64;

    // ---- stage weights / biases / indices ----
    #pragma unroll
    for (int s = 0; s < 16; s++) {           // W2: 256x64 = 4096 float4
        int slot = tid + s * 256;
        int r = slot >> 4, c = slot & 15;
        float4 v = *(const float4*)&W2[r * 64 + c * 4];
        *(float4*)&W2s[r * 68 + c * 4] = v;
    }
    for (int x = tid; x < 64 * 24; x += 256) {   // W3 zero-padded to 24 cols
        int k = x / 24, n = x % 24;
        W3s[k * 36 + n] = (n < 20) ? W3[k * 20 + n] : 0.f;
    }
    if (tid < 64) b2s[tid] = b2[tid];
    if (tid < 24) b3s[tid] = (tid < 20) ? b3[tid] : 0.f;
    if (tid < 20) W4s[tid] = W4[tid];
    if (tid == 0) b4s[0] = b4[0];
    if (tid < 64) {
        int ge = ebase + tid;
        eis[tid] = (ge < nE) ? edge_i[ge] : 0;
        ejs[tid] = (ge < nE) ? edge_j[ge] : 0;
    }
    __syncthreads();

    // ---- gather L[i] + C[j], relu -> h1 (coalesced: 64 threads per 1KB row) ----
    for (int x = tid; x < 64 * 64; x += 256) {
        int e = x >> 6, c = x & 63;
        int ge = ebase + e;
        float4 hv = {0.f, 0.f, 0.f, 0.f};
        if (ge < nE) {
            float4 lv = *(const float4*)&g_L[(size_t)eis[e] * 256 + c * 4];
            float4 cv = *(const float4*)&g_C[(size_t)ejs[e] * 256 + c * 4];
            hv.x = fmaxf(lv.x + cv.x, 0.f);
            hv.y = fmaxf(lv.y + cv.y, 0.f);
            hv.z = fmaxf(lv.z + cv.z, 0.f);
            hv.w = fmaxf(lv.w + cv.w, 0.f);
        }
        *(float4*)&h1[e * 260 + c * 4] = hv;
    }
    __syncthreads();

    // ---- layer 2: h2[64,64] = relu(h1[64,256] @ W2 + b2), tf32 mma ----
    {
        const int rb = (warp & 3) * 16;
        const int cb = (warp >> 2) * 32;
        float acc[4][4] = {};
        for (int k8 = 0; k8 < 32; k8++) {
            const int kc = k8 * 8;
            unsigned a[4];
            a[0] = f2tf(h1[(rb + g    ) * 260 + kc + t4    ]);
            a[1] = f2tf(h1[(rb + g + 8) * 260 + kc + t4    ]);
            a[2] = f2tf(h1[(rb + g    ) * 260 + kc + t4 + 4]);
            a[3] = f2tf(h1[(rb + g + 8) * 260 + kc + t4 + 4]);
            #pragma unroll
            for (int ni = 0; ni < 4; ni++) {
                unsigned b[2];
                int col = cb + ni * 8 + g;
                b[0] = f2tf(W2s[(kc + t4    ) * 68 + col]);
                b[1] = f2tf(W2s[(kc + t4 + 4) * 68 + col]);
                mma_tf32(acc[ni], a, b);
            }
        }
        #pragma unroll
        for (int ni = 0; ni < 4; ni++) {
            int col = cb + ni * 8 + t4 * 2;
            float bb0 = b2s[col], bb1 = b2s[col + 1];
            float2 v0 = {fmaxf(acc[ni][0] + bb0, 0.f), fmaxf(acc[ni][1] + bb1, 0.f)};
            float2 v1 = {fmaxf(acc[ni][2] + bb0, 0.f), fmaxf(acc[ni][3] + bb1, 0.f)};
            *(float2*)&h2[(rb + g    ) * 68 + col] = v0;
            *(float2*)&h2[(rb + g + 8) * 68 + col] = v1;
        }
    }
    __syncthreads();

    // ---- layer 3: h3[64,24] = relu(h2[64,64] @ W3pad + b3), warps 0..3 ----
    if (warp < 4) {
        const int rb = warp * 16;
        float acc[3][4] = {};
        #pragma unroll
        for (int k8 = 0; k8 < 8; k8++) {
            const int kc = k8 * 8;
            unsigned a[4];
            a[0] = f2tf(h2[(rb + g    ) * 68 + kc + t4    ]);
            a[1] = f2tf(h2[(rb + g + 8) * 68 + kc + t4    ]);
            a[2] = f2tf(h2[(rb + g    ) * 68 + kc + t4 + 4]);
            a[3] = f2tf(h2[(rb + g + 8) * 68 + kc + t4 + 4]);
            #pragma unroll
            for (int ni = 0; ni < 3; ni++) {
                unsigned b[2];
                int col = ni * 8 + g;
                b[0] = f2tf(W3s[(kc + t4    ) * 36 + col]);
                b[1] = f2tf(W3s[(kc + t4 + 4) * 36 + col]);
                mma_tf32(acc[ni], a, b);
            }
        }
        #pragma unroll
        for (int ni = 0; ni < 3; ni++) {
            int col = ni * 8 + t4 * 2;
            float bb0 = b3s[col], bb1 = b3s[col + 1];
            float2 v0 = {fmaxf(acc[ni][0] + bb0, 0.f), fmaxf(acc[ni][1] + bb1, 0.f)};
            float2 v1 = {fmaxf(acc[ni][2] + bb0, 0.f), fmaxf(acc[ni][3] + bb1, 0.f)};
            *(float2*)&h3[(rb + g    ) * 36 + col] = v0;
            *(float2*)&h3[(rb + g + 8) * 36 + col] = v1;
        }
    }
    __syncthreads();

    // ---- layer 4 + per-clause atomic accumulation ----
    if (tid < 64) {
        int ge = ebase + tid;
        if (ge < nE) {
            float w = b4s[0];
            #pragma unroll
            for (int j = 0; j < 20; j++) w += h3[tid * 36 + j] * W4s[j];
            int cl = ejs[tid];
            atomicAdd(&g_sums[cl], w);
            atomicAdd(&g_cnts[cl], 1.0f);
        }
    }
}

// ----------------------------------------------------------------------------
// Finalize: out[e] = mean of edge e's clause (tables are L2-resident).
// ----------------------------------------------------------------------------
__global__ void finalize_kernel(const int* __restrict__ edge_j,
                                float* __restrict__ out, int nE) {
    int e = blockIdx.x * blockDim.x + threadIdx.x;
    if (e < nE) {
        int j = edge_j[e];
        out[e] = g_sums[j] / fmaxf(g_cnts[j], 1.0f);
    }
}

// ----------------------------------------------------------------------------
extern "C" void kernel_launch(void* const* d_in, const int* in_sizes, int n_in,
                              void* d_out, int out_size)
{
    const float* l_embs = (const float*)d_in[0];
    const float* c_embs = (const float*)d_in[1];
    const int*   edge_i = (const int*)d_in[2];
    const int*   edge_j = (const int*)d_in[3];
    const float* W1     = (const float*)d_in[4];
    const float* b1     = (const float*)d_in[5];
    const float* W2     = (const float*)d_in[6];
    const float* b2     = (const float*)d_in[7];
    const float* W3     = (const float*)d_in[8];
    const float* b3     = (const float*)d_in[9];
    const float* W4     = (const float*)d_in[10];
    const float* b4     = (const float*)d_in[11];
    float* out = (float*)d_out;

    const int nL = in_sizes[0] / 384;   // 131072
    const int nC = in_sizes[1] / 384;   // 65536
    const int nE = in_sizes[2];         // 524288

    cudaFuncSetAttribute(edge_kernel,
                         cudaFuncAttributeMaxDynamicSharedMemorySize,
                         EDGE_SMEM_BYTES);

    dim3 gL(nL / 128, 2), gC(nC / 128, 2);
    gemm384x256<true ><<<gL, 256>>>(l_embs, W1,             b1);
    gemm384x256<false><<<gC, 256>>>(c_embs, W1 + 384 * 256, nullptr);
    zero_kernel<<<(nC + 255) / 256, 256>>>(nC);
    edge_kernel<<<(nE + 63) / 64, 256, EDGE_SMEM_BYTES>>>(
        edge_i, edge_j, W2, b2, W3, b3, W4, b4, nE);
    finalize_kernel<<<(nE + 255) / 256, 256>>>(edge_j, out, nE);
}

// round 8
// speedup vs baseline: 1.7731x; 1.7731x over previous
#include <cuda_runtime.h>
#include <cstdint>
#include <cstddef>

// ============================================================================
// MLP_SAT v2: factorized edge-MLP + segment mean, latency-optimized.
//   gemm_LC (merged): L = l_embs@W1a + b1 ; C = c_embs@W1b   (tf32 mma)
//   edge_kernel: 128 edges/block, 2 CTAs/SM, K-chunked pipelined layer-2,
//                all smem operands pre-converted to tf32 (u32).
// ============================================================================

#define NLITS 131072
#define NCLS  65536

__device__ float g_L[(size_t)NLITS * 256];
__device__ float g_C[(size_t)NCLS * 256];
__device__ float g_sums[NCLS];
__device__ float g_cnts[NCLS];

__device__ __forceinline__ unsigned f2tf(float x) {
    unsigned r;
    asm("cvt.rna.tf32.f32 %0, %1;" : "=r"(r) : "f"(x));
    return r;
}

__device__ __forceinline__ void mma_tf32(float* d, const unsigned* a, const unsigned* b) {
    asm volatile(
        "mma.sync.aligned.m16n8k8.row.col.f32.tf32.tf32.f32 "
        "{%0,%1,%2,%3}, {%4,%5,%6,%7}, {%8,%9}, {%0,%1,%2,%3};\n"
        : "+f"(d[0]), "+f"(d[1]), "+f"(d[2]), "+f"(d[3])
        : "r"(a[0]), "r"(a[1]), "r"(a[2]), "r"(a[3]), "r"(b[0]), "r"(b[1]));
}

// ----------------------------------------------------------------------------
// Merged GEMM: rows [0,nL) -> g_L = l_embs@W1[0:384]+b1 ; rows [nL,nL+nC) ->
// g_C = c_embs@W1[384:768]. BM=128,BN=128,BK=32; operands pre-cvt to tf32.
// ----------------------------------------------------------------------------
__global__ __launch_bounds__(256) void gemm_LC(
    const float* __restrict__ l_embs, const float* __restrict__ c_embs,
    const float* __restrict__ W1, const float* __restrict__ b1, int nL)
{
    __shared__ unsigned As[128 * 36];   // tf32; bank = (4r + c) % 32
    __shared__ unsigned Ws[32 * 132];   // tf32

    const int tid  = threadIdx.x;
    const int warp = tid >> 5, lane = tid & 31;
    const int g = lane >> 2, t4 = lane & 3;
    const int wm = warp & 3, wn = warp >> 2;
    const int rowBase = blockIdx.x * 128;
    const int colBase = blockIdx.y * 128;

    const bool isL = rowBase < nL;
    const float* __restrict__ A = isL ? l_embs + (size_t)rowBase * 384
                                      : c_embs + (size_t)(rowBase - nL) * 384;
    const float* __restrict__ W = isL ? W1 : W1 + (size_t)384 * 256;
    float* __restrict__ out = isL ? g_L + (size_t)rowBase * 256
                                  : g_C + (size_t)(rowBase - nL) * 256;

    float acc[2][8][4];
    #pragma unroll
    for (int mi = 0; mi < 2; mi++)
        #pragma unroll
        for (int ni = 0; ni < 8; ni++)
            #pragma unroll
            for (int q = 0; q < 4; q++) acc[mi][ni][q] = 0.f;

    for (int kt = 0; kt < 384; kt += 32) {
        #pragma unroll
        for (int s = 0; s < 4; s++) {           // A tile: 128x32
            int slot = tid + s * 256;
            int r = slot >> 3, c = slot & 7;
            float4 v = *(const float4*)&A[(size_t)r * 384 + kt + c * 4];
            uint4 u = {f2tf(v.x), f2tf(v.y), f2tf(v.z), f2tf(v.w)};
            *(uint4*)&As[r * 36 + c * 4] = u;
        }
        #pragma unroll
        for (int s = 0; s < 4; s++) {           // W tile: 32x128
            int slot = tid + s * 256;
            int r = slot >> 5, c = slot & 31;
            float4 v = *(const float4*)&W[(size_t)(kt + r) * 256 + colBase + c * 4];
            uint4 u = {f2tf(v.x), f2tf(v.y), f2tf(v.z), f2tf(v.w)};
            *(uint4*)&Ws[r * 132 + c * 4] = u;
        }
        __syncthreads();

        #pragma unroll
        for (int k8 = 0; k8 < 4; k8++) {
            const int kc = k8 * 8;
            unsigned afr[2][4];
            #pragma unroll
            for (int mi = 0; mi < 2; mi++) {
                int rb = wm * 32 + mi * 16;
                afr[mi][0] = As[(rb + g    ) * 36 + kc + t4    ];
                afr[mi][1] = As[(rb + g + 8) * 36 + kc + t4    ];
                afr[mi][2] = As[(rb + g    ) * 36 + kc + t4 + 4];
                afr[mi][3] = As[(rb + g + 8) * 36 + kc + t4 + 4];
            }
            #pragma unroll
            for (int ni = 0; ni < 8; ni++) {
                unsigned bfr[2];
                int col = wn * 64 + ni * 8 + g;
                bfr[0] = Ws[(kc + t4    ) * 132 + col];
                bfr[1] = Ws[(kc + t4 + 4) * 132 + col];
                mma_tf32(acc[0][ni], afr[0], bfr);
                mma_tf32(acc[1][ni], afr[1], bfr);
            }
        }
        __syncthreads();
    }

    #pragma unroll
    for (int mi = 0; mi < 2; mi++) {
        #pragma unroll
        for (int ni = 0; ni < 8; ni++) {
            int r0 = wm * 32 + mi * 16 + g;
            int c0 = colBase + wn * 64 + ni * 8 + t4 * 2;
            float bb0 = isL ? b1[c0]     : 0.f;
            float bb1 = isL ? b1[c0 + 1] : 0.f;
            float2 v0 = {acc[mi][ni][0] + bb0, acc[mi][ni][1] + bb1};
            float2 v1 = {acc[mi][ni][2] + bb0, acc[mi][ni][3] + bb1};
            *(float2*)&out[(size_t)r0 * 256 + c0] = v0;
            *(float2*)&out[(size_t)(r0 + 8) * 256 + c0] = v1;
        }
    }
}

// ----------------------------------------------------------------------------
__global__ void zero_kernel(int n) {
    int i = blockIdx.x * blockDim.x + threadIdx.x;
    if (i < n) { g_sums[i] = 0.f; g_cnts[i] = 0.f; }
}

// ----------------------------------------------------------------------------
// Edge kernel: 128 edges/block, 256 threads, 2 CTAs/SM.
// smem (u32 words):
//   W2p  [16384]  W2 as tf32 uint2 k-pairs: slot=((k8*64+n)*4+(k&3))*2+(k>>2&1)
//                 -> reused as h2[128][68] after layer 2
//   h1c  [4608]   32-channel chunk of h1, [128][36]  -> reused as h3[128][25] f32
//   W3p  [1536]   W3 (N padded to 24) as tf32 uint2 k-pairs
//   b2s/b3s/W4s/b4s/eis/ejs
// ----------------------------------------------------------------------------
#define EK_SMEM_WORDS (16384 + 4608 + 1536 + 64 + 24 + 20 + 4 + 256)
#define EK_SMEM_BYTES (EK_SMEM_WORDS * 4)

__global__ __launch_bounds__(256, 2) void edge_kernel(
    const int* __restrict__ edge_i, const int* __restrict__ edge_j,
    const float* __restrict__ W2, const float* __restrict__ b2,
    const float* __restrict__ W3, const float* __restrict__ b3,
    const float* __restrict__ W4, const float* __restrict__ b4,
    int nE)
{
    extern __shared__ unsigned smu[];
    unsigned* W2p = smu;                    // 16384
    unsigned* h1c = W2p + 16384;            // 4608
    unsigned* W3p = h1c + 4608;             // 1536
    float* b2s = (float*)(W3p + 1536);      // 64
    float* b3s = b2s + 64;                  // 24
    float* W4s = b3s + 24;                  // 20
    float* b4s = W4s + 20;                  // 4
    int*   eis = (int*)(b4s + 4);           // 128
    int*   ejs = eis + 128;                 // 128
    unsigned* h2 = W2p;                     // [128][68] u32, reuse
    float*    h3 = (float*)h1c;             // [128][25] f32, reuse

    const int tid  = threadIdx.x;
    const int warp = tid >> 5, lane = tid & 31;
    const int g = lane >> 2, t4 = lane & 3;
    const int wm = warp & 3, wn = warp >> 2;     // layer-2 warp grid 4m x 2n
    const int ebase = blockIdx.x * 128;

    // ---- stage W2 -> tf32 k-pair layout ----
    #pragma unroll
    for (int s = 0; s < 16; s++) {
        int x4 = tid + s * 256;              // 4096 float4 = 256x64
        int r = x4 >> 4;                     // k row
        int n0 = (x4 & 15) * 4;
        float4 v = *(const float4*)&W2[r * 64 + n0];
        int k8 = r >> 3, tl = r & 3, th = (r >> 2) & 1;
        W2p[((k8 * 64 + n0    ) * 4 + tl) * 2 + th] = f2tf(v.x);
        W2p[((k8 * 64 + n0 + 1) * 4 + tl) * 2 + th] = f2tf(v.y);
        W2p[((k8 * 64 + n0 + 2) * 4 + tl) * 2 + th] = f2tf(v.z);
        W2p[((k8 * 64 + n0 + 3) * 4 + tl) * 2 + th] = f2tf(v.w);
    }
    // ---- stage W3 (zero-padded to 24 cols) ----
    for (int x = tid; x < 64 * 24; x += 256) {
        int k = x / 24, n = x % 24;
        float val = (n < 20) ? W3[k * 20 + n] : 0.f;
        int k8 = k >> 3, tl = k & 3, th = (k >> 2) & 1;
        W3p[((k8 * 24 + n) * 4 + tl) * 2 + th] = f2tf(val);
    }
    if (tid < 64) b2s[tid] = b2[tid];
    if (tid < 24) b3s[tid] = (tid < 20) ? b3[tid] : 0.f;
    if (tid < 20) W4s[tid] = W4[tid];
    if (tid == 0) b4s[0] = b4[0];
    if (tid < 128) {
        int ge = ebase + tid;
        eis[tid] = (ge < nE) ? edge_i[ge] : 0;
        ejs[tid] = (ge < nE) ? edge_j[ge] : 0;
    }
    __syncthreads();

    // ---- layer 2: K chunked by 32, gather pipelined against mma ----
    float acc[2][4][4];
    #pragma unroll
    for (int mi = 0; mi < 2; mi++)
        #pragma unroll
        for (int ni = 0; ni < 4; ni++)
            #pragma unroll
            for (int q = 0; q < 4; q++) acc[mi][ni][q] = 0.f;

    float4 Lr[4], Cr[4];
    // prologue: load chunk 0 (each thread: 4 float4 L + 4 float4 C)
    #pragma unroll
    for (int s = 0; s < 4; s++) {
        int x = tid + s * 256;
        int e = x >> 3, q = (x & 7) * 4;
        Lr[s] = *(const float4*)&g_L[(size_t)eis[e] * 256 + q];
        Cr[s] = *(const float4*)&g_C[(size_t)ejs[e] * 256 + q];
    }

    for (int c = 0; c < 8; c++) {
        // deposit chunk c (relu(L+C) -> tf32) into h1c
        #pragma unroll
        for (int s = 0; s < 4; s++) {
            int x = tid + s * 256;
            int e = x >> 3, q = (x & 7) * 4;
            uint4 hv;
            hv.x = f2tf(fmaxf(Lr[s].x + Cr[s].x, 0.f));
            hv.y = f2tf(fmaxf(Lr[s].y + Cr[s].y, 0.f));
            hv.z = f2tf(fmaxf(Lr[s].z + Cr[s].z, 0.f));
            hv.w = f2tf(fmaxf(Lr[s].w + Cr[s].w, 0.f));
            *(uint4*)&h1c[e * 36 + q] = hv;
        }
        __syncthreads();
        // prefetch chunk c+1 while mma runs
        if (c < 7) {
            int kk = (c + 1) * 32;
            #pragma unroll
            for (int s = 0; s < 4; s++) {
                int x = tid + s * 256;
                int e = x >> 3, q = (x & 7) * 4;
                Lr[s] = *(const float4*)&g_L[(size_t)eis[e] * 256 + kk + q];
                Cr[s] = *(const float4*)&g_C[(size_t)ejs[e] * 256 + kk + q];
            }
        }
        // mma over this 32-channel chunk
        #pragma unroll
        for (int k8 = 0; k8 < 4; k8++) {
            const int kc = k8 * 8;
            unsigned a[2][4];
            #pragma unroll
            for (int mi = 0; mi < 2; mi++) {
                int rb = wm * 32 + mi * 16;
                a[mi][0] = h1c[(rb + g    ) * 36 + kc + t4    ];
                a[mi][1] = h1c[(rb + g + 8) * 36 + kc + t4    ];
                a[mi][2] = h1c[(rb + g    ) * 36 + kc + t4 + 4];
                a[mi][3] = h1c[(rb + g + 8) * 36 + kc + t4 + 4];
            }
            const int k8g = c * 4 + k8;
            #pragma unroll
            for (int ni = 0; ni < 4; ni++) {
                int col = wn * 32 + ni * 8 + g;
                uint2 bp = *(const uint2*)&W2p[((k8g * 64 + col) * 4 + t4) * 2];
                unsigned b[2] = {bp.x, bp.y};
                mma_tf32(acc[0][ni], a[0], b);
                mma_tf32(acc[1][ni], a[1], b);
            }
        }
        __syncthreads();
    }

    // ---- layer-2 epilogue: h2 = relu(acc + b2) as tf32, into W2p region ----
    #pragma unroll
    for (int mi = 0; mi < 2; mi++) {
        #pragma unroll
        for (int ni = 0; ni < 4; ni++) {
            int row0 = wm * 32 + mi * 16 + g;
            int col  = wn * 32 + ni * 8 + t4 * 2;
            float bb0 = b2s[col], bb1 = b2s[col + 1];
            h2[ row0      * 68 + col    ] = f2tf(fmaxf(acc[mi][ni][0] + bb0, 0.f));
            h2[ row0      * 68 + col + 1] = f2tf(fmaxf(acc[mi][ni][1] + bb1, 0.f));
            h2[(row0 + 8) * 68 + col    ] = f2tf(fmaxf(acc[mi][ni][2] + bb0, 0.f));
            h2[(row0 + 8) * 68 + col + 1] = f2tf(fmaxf(acc[mi][ni][3] + bb1, 0.f));
        }
    }
    __syncthreads();

    // ---- layer 3: h3[128,24] = relu(h2[128,64] @ W3p + b3); all 8 warps ----
    {
        const int rb3 = warp * 16;
        float a3[3][4];
        #pragma unroll
        for (int ni = 0; ni < 3; ni++)
            #pragma unroll
            for (int q = 0; q < 4; q++) a3[ni][q] = 0.f;

        #pragma unroll
        for (int k8 = 0; k8 < 8; k8++) {
            const int kc = k8 * 8;
            unsigned a[4];
            a[0] = h2[(rb3 + g    ) * 68 + kc + t4    ];
            a[1] = h2[(rb3 + g + 8) * 68 + kc + t4    ];
            a[2] = h2[(rb3 + g    ) * 68 + kc + t4 + 4];
            a[3] = h2[(rb3 + g + 8) * 68 + kc + t4 + 4];
            #pragma unroll
            for (int ni = 0; ni < 3; ni++) {
                int col = ni * 8 + g;
                uint2 bp = *(const uint2*)&W3p[((k8 * 24 + col) * 4 + t4) * 2];
                unsigned b[2] = {bp.x, bp.y};
                mma_tf32(a3[ni], a, b);
            }
        }
        // h3 into old h1c region (free after last chunk's mma + sync)
        #pragma unroll
        for (int ni = 0; ni < 3; ni++) {
            int col = ni * 8 + t4 * 2;
            float bb0 = b3s[col], bb1 = b3s[col + 1];
            h3[(rb3 + g    ) * 25 + col    ] = fmaxf(a3[ni][0] + bb0, 0.f);
            h3[(rb3 + g    ) * 25 + col + 1] = fmaxf(a3[ni][1] + bb1, 0.f);
            h3[(rb3 + g + 8) * 25 + col    ] = fmaxf(a3[ni][2] + bb0, 0.f);
            h3[(rb3 + g + 8) * 25 + col + 1] = fmaxf(a3[ni][3] + bb1, 0.f);
        }
    }
    __syncthreads();

    // ---- layer 4 + per-clause atomic accumulation ----
    if (tid < 128) {
        int ge = ebase + tid;
        if (ge < nE) {
            float w = b4s[0];
            #pragma unroll
            for (int j = 0; j < 20; j++) w += h3[tid * 25 + j] * W4s[j];
            int cl = ejs[tid];
            atomicAdd(&g_sums[cl], w);
            atomicAdd(&g_cnts[cl], 1.0f);
        }
    }
}

// ----------------------------------------------------------------------------
__global__ void finalize_kernel(const int* __restrict__ edge_j,
                                float* __restrict__ out, int nE) {
    int e = blockIdx.x * blockDim.x + threadIdx.x;
    if (e < nE) {
        int j = edge_j[e];
        out[e] = g_sums[j] / fmaxf(g_cnts[j], 1.0f);
    }
}

// ----------------------------------------------------------------------------
extern "C" void kernel_launch(void* const* d_in, const int* in_sizes, int n_in,
                              void* d_out, int out_size)
{
    const float* l_embs = (const float*)d_in[0];
    const float* c_embs = (const float*)d_in[1];
    const int*   edge_i = (const int*)d_in[2];
    const int*   edge_j = (const int*)d_in[3];
    const float* W1     = (const float*)d_in[4];
    const float* b1     = (const float*)d_in[5];
    const float* W2     = (const float*)d_in[6];
    const float* b2     = (const float*)d_in[7];
    const float* W3     = (const float*)d_in[8];
    const float* b3     = (const float*)d_in[9];
    const float* W4     = (const float*)d_in[10];
    const float* b4     = (const float*)d_in[11];
    float* out = (float*)d_out;

    const int nL = in_sizes[0] / 384;   // 131072
    const int nC = in_sizes[1] / 384;   // 65536
    const int nE = in_sizes[2];         // 524288

    cudaFuncSetAttribute(edge_kernel,
                         cudaFuncAttributeMaxDynamicSharedMemorySize,
                         EK_SMEM_BYTES);

    gemm_LC<<<dim3((nL + nC) / 128, 2), 256>>>(l_embs, c_embs, W1, b1, nL);
    zero_kernel<<<(nC + 255) / 256, 256>>>(nC);
    edge_kernel<<<(nE + 127) / 128, 256, EK_SMEM_BYTES>>>(
        edge_i, edge_j, W2, b2, W3, b3, W4, b4, nE);
    finalize_kernel<<<(nE + 255) / 256, 256>>>(edge_j, out, nE);
}